// round 6
// baseline (speedup 1.0000x reference)
#include <cuda_runtime.h>
#include <math.h>

#define B_ 512
#define T_ 256
#define N_ 128
#define M_ 256
#define FM_ 1024   // 4*M

// ---------------- scratch (device globals: allocation-free) ----------------
__device__ float g_r2[(size_t)B_ * N_ * T_];          // [b][n][u]      67 MB
__device__ float g_Xk[(size_t)T_ * B_ * FM_];         // [t][b][4M]    537 MB
__device__ float g_H[(size_t)(T_ + 1) * B_ * M_];     // carry history 135 MB
__device__ float g_S[(size_t)(T_ + 1) * B_ * M_];     // carry history 135 MB
__device__ float g_R1[(size_t)T_ * B_ * T_];          // [tau][b][u]   134 MB
__device__ float g_Wrt[(size_t)M_ * FM_];             // Wr as [k][m][gate] 1 MB

__device__ __forceinline__ float sigm(float x) {
    return 1.0f / (1.0f + __expf(-x));
}
// accurate-enough tanh: rel err ~1e-6, 2 MUFU
__device__ __forceinline__ float tanh_e(float x) {
    float a = fabsf(x);
    float e = __expf(-2.0f * a);
    float r = __fdividef(1.0f - e, 1.0f + e);
    return copysignf(r, x);
}

// ---- init: history slot 0 <- (h, s); transpose Wr to gate-interleaved ----
__global__ void k_init(const float* __restrict__ s, const float* __restrict__ h,
                       const float* __restrict__ Wr) {
    int i = blockIdx.x * blockDim.x + threadIdx.x;
    if (i < B_ * M_) {
        g_H[i] = h[i];
        g_S[i] = s[i];
    }
    if (i < M_ * FM_) {
        int k = i >> 10;        // Wr row 0..255
        int c = i & 1023;       // Wr col 0..1023
        int g = c >> 8;         // gate 0..3 (i,f,c,o)
        int m = c & 255;
        g_Wrt[((size_t)(k * 256 + m)) * 4 + g] = Wr[i];
    }
}

// ---- r2[b][n][u] = sum_t x[b][t][n] * Ue[t][u] ----
// grid (B, 4): per block one b, 64 u-cols, all 128 n. block 256.
__global__ __launch_bounds__(256) void k_r2(const float* __restrict__ x,
                                            const float* __restrict__ Ue) {
    int b = blockIdx.x;
    int ut = blockIdx.y * 64;
    __shared__ float xs[32][128];  // [t][n]
    __shared__ float us[32][64];   // [t][u]
    int tid = threadIdx.x;
    int n0 = (tid & 31) * 4;       // 4 n per thread
    int u0 = (tid >> 5) * 8;       // 8 u per thread

    float acc[8][4];
#pragma unroll
    for (int j = 0; j < 8; j++)
#pragma unroll
        for (int i = 0; i < 4; i++) acc[j][i] = 0.f;

    for (int kt = 0; kt < T_; kt += 32) {
#pragma unroll
        for (int l = 0; l < 4; l++) {
            int idx = l * 256 + tid;
            int t = idx >> 5, n4 = idx & 31;
            *(float4*)&xs[t][n4 * 4] =
                ((const float4*)x)[(size_t)(b * T_ + kt + t) * 32 + n4];
        }
#pragma unroll
        for (int l = 0; l < 2; l++) {
            int idx = l * 256 + tid;
            int t = idx >> 4, u4 = idx & 15;
            *(float4*)&us[t][u4 * 4] =
                ((const float4*)Ue)[(size_t)(kt + t) * 64 + (ut >> 2) + u4];
        }
        __syncthreads();
#pragma unroll 8
        for (int k = 0; k < 32; k++) {
            float4 x4 = *(const float4*)&xs[k][n0];
            float4 ua = *(const float4*)&us[k][u0];
            float4 ub = *(const float4*)&us[k][u0 + 4];
            float xv[4] = {x4.x, x4.y, x4.z, x4.w};
            float uu[8] = {ua.x, ua.y, ua.z, ua.w, ub.x, ub.y, ub.z, ub.w};
#pragma unroll
            for (int j = 0; j < 8; j++)
#pragma unroll
                for (int i = 0; i < 4; i++) acc[j][i] += xv[i] * uu[j];
        }
        __syncthreads();
    }
#pragma unroll
    for (int i = 0; i < 4; i++) {
        size_t base = ((size_t)(b * N_ + n0 + i)) * T_ + ut + u0;
        *(float4*)&g_r2[base] = make_float4(acc[0][i], acc[1][i], acc[2][i], acc[3][i]);
        *(float4*)&g_r2[base + 4] = make_float4(acc[4][i], acc[5][i], acc[6][i], acc[7][i]);
    }
}

// ---- Xk[t][b][c] = x[b][t][:] @ Wk[:,c] + bias[c]  (rows flat rbt = b*T+t) ----
// grid (4096, 4): 32 rows x 256 cols per block. block 256.
__global__ __launch_bounds__(256) void k_xk(const float* __restrict__ x,
                                            const float* __restrict__ Wk,
                                            const float* __restrict__ bias) {
    int rb = blockIdx.x;
    int tid = threadIdx.x;
    int c0 = blockIdx.y * 256 + (tid & 63) * 4;
    int rt = tid >> 6;  // 0..3, 8 rows each
    __shared__ float as[32][128];
#pragma unroll
    for (int l = 0; l < 4; l++) {
        int idx = l * 256 + tid;
        int r = idx >> 5, n4 = idx & 31;
        *(float4*)&as[r][n4 * 4] =
            ((const float4*)x)[(size_t)(rb * 32 + r) * 32 + n4];
    }
    __syncthreads();
    float acc[8][4];
#pragma unroll
    for (int i = 0; i < 8; i++)
#pragma unroll
        for (int j = 0; j < 4; j++) acc[i][j] = 0.f;
#pragma unroll 4
    for (int k = 0; k < 128; k++) {
        float4 w = ((const float4*)Wk)[(size_t)k * 256 + (c0 >> 2)];
#pragma unroll
        for (int i = 0; i < 8; i++) {
            float a = as[rt * 8 + i][k];
            acc[i][0] += a * w.x;
            acc[i][1] += a * w.y;
            acc[i][2] += a * w.z;
            acc[i][3] += a * w.w;
        }
    }
    float4 bv = ((const float4*)bias)[c0 >> 2];
#pragma unroll
    for (int i = 0; i < 8; i++) {
        int rbt = rb * 32 + rt * 8 + i;
        int b = rbt >> 8;    // / T_
        int t = rbt & 255;
        float4 v = make_float4(acc[i][0] + bv.x, acc[i][1] + bv.y,
                               acc[i][2] + bv.z, acc[i][3] + bv.w);
        ((float4*)g_Xk)[((size_t)t * B_ + b) * 256 + (c0 >> 2)] = v;
    }
}

// ---- one LSTM step: z = Xk[t] + H[t] @ Wr; gates; write H[t+1], S[t+1] ----
// grid (16, 8): 32 b-rows x 32 m (all 4 gates). block 256.
__global__ __launch_bounds__(256) void k_lstm(int t) {
    int bx = blockIdx.x, by = blockIdx.y;
    int tid = threadIdx.x;
    int m = by * 32 + (tid & 31);
    int rt = tid >> 5;  // 0..7, 4 rows each
    __shared__ float hs[32][256];
#pragma unroll
    for (int l = 0; l < 8; l++) {
        int idx = l * 256 + tid;
        int r = idx >> 6, j4 = idx & 63;
        *(float4*)&hs[r][j4 * 4] =
            ((const float4*)g_H)[((size_t)t * B_ + bx * 32 + r) * 64 + j4];
    }
    __syncthreads();
    float acc[4][4];
#pragma unroll
    for (int i = 0; i < 4; i++)
#pragma unroll
        for (int g = 0; g < 4; g++) acc[i][g] = 0.f;
#pragma unroll 4
    for (int k = 0; k < 256; k++) {
        float4 w = ((const float4*)g_Wrt)[(size_t)k * 256 + m];
#pragma unroll
        for (int i = 0; i < 4; i++) {
            float hv = hs[rt * 4 + i][k];
            acc[i][0] += hv * w.x;
            acc[i][1] += hv * w.y;
            acc[i][2] += hv * w.z;
            acc[i][3] += hv * w.w;
        }
    }
#pragma unroll
    for (int i = 0; i < 4; i++) {
        int b = bx * 32 + rt * 4 + i;
        size_t xo = ((size_t)t * B_ + b) * FM_ + m;
        float zi = acc[i][0] + g_Xk[xo];
        float zf = acc[i][1] + g_Xk[xo + 256];
        float zg = acc[i][2] + g_Xk[xo + 512];
        float zo = acc[i][3] + g_Xk[xo + 768];
        float ig = sigm(zi), fg = sigm(zf), og = sigm(zo);
        float gg = tanh_e(zg);
        size_t so = ((size_t)t * B_ + b) * M_ + m;
        float sn = fg * g_S[so] + ig * gg;
        float hn = og * tanh_e(sn);
        size_t dn = ((size_t)(t + 1) * B_ + b) * M_ + m;
        g_S[dn] = sn;
        g_H[dn] = hn;
    }
}

// ---- R1[tau][b][u] = concat(H[tau][b], S[tau][b]) @ We[:,u] ----
// rows flat = tau*B + b. grid 4096: 32 rows x 256 cols. block 256.
__global__ __launch_bounds__(256) void k_R1(const float* __restrict__ We) {
    int rb = blockIdx.x;
    int tid = threadIdx.x;
    int u0 = (tid & 63) * 4;
    int rt = tid >> 6;  // 0..3, 8 rows each
    __shared__ float as[32][64];
    float acc[8][4];
#pragma unroll
    for (int i = 0; i < 8; i++)
#pragma unroll
        for (int j = 0; j < 4; j++) acc[i][j] = 0.f;

    for (int ch = 0; ch < 8; ch++) {
        const float* src = (ch < 4) ? g_H : g_S;
        int boff = (ch & 3) * 16;  // float4 offset within row
        __syncthreads();
#pragma unroll
        for (int l = 0; l < 2; l++) {
            int idx = l * 256 + tid;
            int r = idx >> 4, j4 = idx & 15;
            *(float4*)&as[r][j4 * 4] =
                ((const float4*)src)[(size_t)(rb * 32 + r) * 64 + boff + j4];
        }
        __syncthreads();
#pragma unroll 4
        for (int kk = 0; kk < 64; kk++) {
            float4 w = ((const float4*)We)[(size_t)(ch * 64 + kk) * 64 + (u0 >> 2)];
#pragma unroll
            for (int i = 0; i < 8; i++) {
                float a = as[rt * 8 + i][kk];
                acc[i][0] += a * w.x;
                acc[i][1] += a * w.y;
                acc[i][2] += a * w.z;
                acc[i][3] += a * w.w;
            }
        }
    }
#pragma unroll
    for (int i = 0; i < 8; i++) {
        ((float4*)g_R1)[(size_t)(rb * 32 + rt * 8 + i) * 64 + (u0 >> 2)] =
            make_float4(acc[i][0], acc[i][1], acc[i][2], acc[i][3]);
    }
}

// ---- fused: e = tanh(R1 + r2) @ ve ; softmax over n ; out = alpha * x ----
// grid (B, 8), block 512 (4 tau-lanes x 128 n). r2[b] parked in dynamic smem,
// reused across 32 tau. pad 260 -> conflict-free LDS.128.
__global__ __launch_bounds__(512) void k_e(const float* __restrict__ x,
                                           const float* __restrict__ ve,
                                           float* __restrict__ out) {
    extern __shared__ float r2s[];   // 128 * 260 floats
    __shared__ float r1s[4][256];
    __shared__ float ves[256];
    __shared__ float redm[16];
    __shared__ float reds[16];
    int b = blockIdx.x;
    int tau0 = blockIdx.y * 32;
    int tid = threadIdx.x;
    int lane = tid & 31;
    int warp = tid >> 5;
    int q = tid >> 7;     // tau lane 0..3
    int n = tid & 127;

    if (tid < 256) ves[tid] = ve[tid];
#pragma unroll
    for (int l = 0; l < 16; l++) {
        int idx = l * 512 + tid;
        int nn = idx >> 6, u4 = idx & 63;
        float4 v = ((const float4*)g_r2)[(size_t)(b * N_ + nn) * 64 + u4];
        *(float4*)&r2s[nn * 260 + u4 * 4] = v;
    }
    __syncthreads();
    const float* rp = &r2s[n * 260];

    for (int ti = 0; ti < 8; ti++) {
#pragma unroll
        for (int l = 0; l < 2; l++) {
            int idx = l * 512 + tid;
            int wh = idx >> 8, u = idx & 255;
            r1s[wh][u] = g_R1[((size_t)(tau0 + ti * 4 + wh) * B_ + b) * T_ + u];
        }
        __syncthreads();
        const float* r1p = r1s[q];
        float acc0 = 0.f, acc1 = 0.f;
#pragma unroll 4
        for (int u4 = 0; u4 < 64; u4++) {
            float4 rv = *(const float4*)&rp[u4 * 4];
            float4 r1 = *(const float4*)&r1p[u4 * 4];
            float4 vv = *(const float4*)&ves[u4 * 4];
            acc0 += tanh_e(r1.x + rv.x) * vv.x;
            acc1 += tanh_e(r1.y + rv.y) * vv.y;
            acc0 += tanh_e(r1.z + rv.z) * vv.z;
            acc1 += tanh_e(r1.w + rv.w) * vv.w;
        }
        float e = acc0 + acc1;

        // softmax over the 128 n in this tau-lane (4 warps)
        float mx = e;
#pragma unroll
        for (int off = 16; off >= 1; off >>= 1)
            mx = fmaxf(mx, __shfl_xor_sync(0xffffffffu, mx, off));
        if (lane == 0) redm[warp] = mx;
        __syncthreads();
        mx = fmaxf(fmaxf(redm[q * 4], redm[q * 4 + 1]),
                   fmaxf(redm[q * 4 + 2], redm[q * 4 + 3]));
        float ex = __expf(e - mx);
        float sm = ex;
#pragma unroll
        for (int off = 16; off >= 1; off >>= 1)
            sm += __shfl_xor_sync(0xffffffffu, sm, off);
        if (lane == 0) reds[warp] = sm;
        __syncthreads();
        sm = reds[q * 4] + reds[q * 4 + 1] + reds[q * 4 + 2] + reds[q * 4 + 3];
        float alpha = ex / sm;

        int tau = tau0 + ti * 4 + q;
        size_t oi = ((size_t)b * T_ + tau) * N_ + n;
        out[oi] = alpha * x[oi];
        __syncthreads();  // protect r1s/redm/reds before next iteration
    }
}

extern "C" void kernel_launch(void* const* d_in, const int* in_sizes, int n_in,
                              void* d_out, int out_size) {
    const float* x  = (const float*)d_in[0];
    const float* s  = (const float*)d_in[1];
    const float* h  = (const float*)d_in[2];
    const float* We = (const float*)d_in[3];
    const float* Ue = (const float*)d_in[4];
    const float* ve = (const float*)d_in[5];
    const float* Wk = (const float*)d_in[6];
    const float* Wr = (const float*)d_in[7];
    const float* bb = (const float*)d_in[8];
    float* out = (float*)d_out;
    (void)in_sizes; (void)n_in; (void)out_size;

    k_init<<<1024, 256>>>(s, h, Wr);
    k_r2<<<dim3(B_, 4), 256>>>(x, Ue);
    k_xk<<<dim3(4096, 4), 256>>>(x, Wk, bb);
    for (int t = 0; t < T_; t++)
        k_lstm<<<dim3(16, 8), 256>>>(t);
    k_R1<<<4096, 256>>>(We);

    const int SME = 128 * 260 * (int)sizeof(float);  // 133120 B dynamic smem
    cudaFuncSetAttribute(k_e, cudaFuncAttributeMaxDynamicSharedMemorySize, SME);
    k_e<<<dim3(B_, 8), 512, SME>>>(x, ve, out);
}

// round 7
// speedup vs baseline: 1.4712x; 1.4712x over previous
#include <cuda_runtime.h>
#include <math.h>

#define B_ 512
#define T_ 256
#define N_ 128
#define M_ 256
#define FM_ 1024   // 4*M
#define GRID_LSTM 128

// ---------------- scratch (device globals: allocation-free) ----------------
__device__ float g_r2[(size_t)B_ * N_ * T_];          // [b][n][u]      67 MB
__device__ float g_Xk[(size_t)T_ * B_ * FM_];         // [t][b][4M]    537 MB
__device__ float g_H[(size_t)(T_ + 1) * B_ * M_];     // carry history 135 MB
__device__ float g_S[(size_t)(T_ + 1) * B_ * M_];     // carry history 135 MB
__device__ float g_R1[(size_t)T_ * B_ * T_];          // [tau][b][u]   134 MB
__device__ float g_Wrt[(size_t)M_ * FM_];             // Wr as [k][m][gate] 1 MB

// grid-barrier state (monotone across graph replays -> deterministic)
__device__ unsigned long long g_arrive;
__device__ volatile unsigned long long g_release;

__device__ __forceinline__ float sigm(float x) {
    return 1.0f / (1.0f + __expf(-x));
}
// accurate tanh: rel err ~1e-6, 2 MUFU
__device__ __forceinline__ float tanh_e(float x) {
    float a = fabsf(x);
    float e = __expf(-2.0f * a);
    float r = __fdividef(1.0f - e, 1.0f + e);
    return copysignf(r, x);
}

// ---- packed f32x2 helpers (FFMA2: B300, PTX-only path) ----
__device__ __forceinline__ unsigned long long fma2(unsigned long long a,
                                                   unsigned long long b,
                                                   unsigned long long c) {
    unsigned long long d;
    asm("fma.rn.f32x2 %0, %1, %2, %3;" : "=l"(d) : "l"(a), "l"(b), "l"(c));
    return d;
}
__device__ __forceinline__ unsigned long long dup2(float x) {
    unsigned long long r;
    asm("mov.b64 %0, {%1, %1};" : "=l"(r) : "f"(x));
    return r;
}
__device__ __forceinline__ void unpack2(unsigned long long p, float& lo, float& hi) {
    asm("mov.b64 {%0, %1}, %2;" : "=f"(lo), "=f"(hi) : "l"(p));
}

// ---- init: history slot 0 <- (h, s); transpose Wr to gate-interleaved ----
__global__ void k_init(const float* __restrict__ s, const float* __restrict__ h,
                       const float* __restrict__ Wr) {
    int i = blockIdx.x * blockDim.x + threadIdx.x;
    if (i < B_ * M_) {
        g_H[i] = h[i];
        g_S[i] = s[i];
    }
    if (i < M_ * FM_) {
        int k = i >> 10;        // Wr row 0..255
        int c = i & 1023;       // Wr col 0..1023
        int g = c >> 8;         // gate 0..3 (i,f,c,o)
        int m = c & 255;
        g_Wrt[((size_t)(k * 256 + m)) * 4 + g] = Wr[i];
    }
}

// ---- r2[b][n][u] = sum_t x[b][t][n] * Ue[t][u] ----
__global__ __launch_bounds__(256) void k_r2(const float* __restrict__ x,
                                            const float* __restrict__ Ue) {
    int b = blockIdx.x;
    int ut = blockIdx.y * 64;
    __shared__ float xs[32][128];
    __shared__ float us[32][64];
    int tid = threadIdx.x;
    int n0 = (tid & 31) * 4;
    int u0 = (tid >> 5) * 8;

    float acc[8][4];
#pragma unroll
    for (int j = 0; j < 8; j++)
#pragma unroll
        for (int i = 0; i < 4; i++) acc[j][i] = 0.f;

    for (int kt = 0; kt < T_; kt += 32) {
#pragma unroll
        for (int l = 0; l < 4; l++) {
            int idx = l * 256 + tid;
            int t = idx >> 5, n4 = idx & 31;
            *(float4*)&xs[t][n4 * 4] =
                ((const float4*)x)[(size_t)(b * T_ + kt + t) * 32 + n4];
        }
#pragma unroll
        for (int l = 0; l < 2; l++) {
            int idx = l * 256 + tid;
            int t = idx >> 4, u4 = idx & 15;
            *(float4*)&us[t][u4 * 4] =
                ((const float4*)Ue)[(size_t)(kt + t) * 64 + (ut >> 2) + u4];
        }
        __syncthreads();
#pragma unroll 8
        for (int k = 0; k < 32; k++) {
            float4 x4 = *(const float4*)&xs[k][n0];
            float4 ua = *(const float4*)&us[k][u0];
            float4 ub = *(const float4*)&us[k][u0 + 4];
            float xv[4] = {x4.x, x4.y, x4.z, x4.w};
            float uu[8] = {ua.x, ua.y, ua.z, ua.w, ub.x, ub.y, ub.z, ub.w};
#pragma unroll
            for (int j = 0; j < 8; j++)
#pragma unroll
                for (int i = 0; i < 4; i++) acc[j][i] += xv[i] * uu[j];
        }
        __syncthreads();
    }
#pragma unroll
    for (int i = 0; i < 4; i++) {
        size_t base = ((size_t)(b * N_ + n0 + i)) * T_ + ut + u0;
        *(float4*)&g_r2[base] = make_float4(acc[0][i], acc[1][i], acc[2][i], acc[3][i]);
        *(float4*)&g_r2[base + 4] = make_float4(acc[4][i], acc[5][i], acc[6][i], acc[7][i]);
    }
}

// ---- Xk[t][b][c] = x[b][t][:] @ Wk[:,c] + bias[c] ----
__global__ __launch_bounds__(256) void k_xk(const float* __restrict__ x,
                                            const float* __restrict__ Wk,
                                            const float* __restrict__ bias) {
    int rb = blockIdx.x;
    int tid = threadIdx.x;
    int c0 = blockIdx.y * 256 + (tid & 63) * 4;
    int rt = tid >> 6;
    __shared__ float as[32][128];
#pragma unroll
    for (int l = 0; l < 4; l++) {
        int idx = l * 256 + tid;
        int r = idx >> 5, n4 = idx & 31;
        *(float4*)&as[r][n4 * 4] =
            ((const float4*)x)[(size_t)(rb * 32 + r) * 32 + n4];
    }
    __syncthreads();
    float acc[8][4];
#pragma unroll
    for (int i = 0; i < 8; i++)
#pragma unroll
        for (int j = 0; j < 4; j++) acc[i][j] = 0.f;
#pragma unroll 4
    for (int k = 0; k < 128; k++) {
        float4 w = ((const float4*)Wk)[(size_t)k * 256 + (c0 >> 2)];
#pragma unroll
        for (int i = 0; i < 8; i++) {
            float a = as[rt * 8 + i][k];
            acc[i][0] += a * w.x;
            acc[i][1] += a * w.y;
            acc[i][2] += a * w.z;
            acc[i][3] += a * w.w;
        }
    }
    float4 bv = ((const float4*)bias)[c0 >> 2];
#pragma unroll
    for (int i = 0; i < 8; i++) {
        int rbt = rb * 32 + rt * 8 + i;
        int b = rbt >> 8;
        int t = rbt & 255;
        float4 v = make_float4(acc[i][0] + bv.x, acc[i][1] + bv.y,
                               acc[i][2] + bv.z, acc[i][3] + bv.w);
        ((float4*)g_Xk)[((size_t)t * B_ + b) * 256 + (c0 >> 2)] = v;
    }
}

// ---- persistent LSTM: all 256 steps in one kernel, grid barrier per step ----
// grid 128 = 16 bx (32 b-rows) x 8 by (32 m-cols). block 256.
// smem: ws (Wr slice, gate-interleaved) 128KB + hd (H[t] rows duplicated (h,h)) 64KB.
__global__ __launch_bounds__(256, 1) void k_lstm_all() {
    extern __shared__ char smc[];
    float* ws = (float*)smc;                                   // [k][32m][4g]
    unsigned long long* hd = (unsigned long long*)(smc + 131072);  // [64 j4*4][32 r] dup
    const ulonglong2* wsv = (const ulonglong2*)ws;
    const ulonglong2* hdv = (const ulonglong2*)hd;

    int tid = threadIdx.x;
    int bx = blockIdx.x & 15;
    int by = blockIdx.x >> 4;
    int ml = tid & 31;          // local m
    int mg = by * 32 + ml;      // global m
    int rt = tid >> 5;          // 0..7 -> rows rt*4..rt*4+3

    // prologue: weights into smem (once)
#pragma unroll
    for (int l = 0; l < 32; l++) {
        int f = l * 256 + tid;          // float4 id: k = f>>5, m = f&31
        int k = f >> 5, mm = f & 31;
        ((float4*)ws)[f] = ((const float4*)g_Wrt)[(size_t)k * 256 + by * 32 + mm];
    }
    __syncthreads();

    for (int t = 0; t < T_; t++) {
        // load H[t] rows [bx*32, +32), duplicated into smem as (h,h) pairs
#pragma unroll
        for (int l = 0; l < 8; l++) {
            int idx = l * 256 + tid;
            int r = idx & 31, j = idx >> 5;   // j = float4 col 0..63
            float4 v = ((const float4*)g_H)[((size_t)t * B_ + bx * 32 + r) * 64 + j];
            hd[(size_t)(j * 4 + 0) * 32 + r] = dup2(v.x);
            hd[(size_t)(j * 4 + 1) * 32 + r] = dup2(v.y);
            hd[(size_t)(j * 4 + 2) * 32 + r] = dup2(v.z);
            hd[(size_t)(j * 4 + 3) * 32 + r] = dup2(v.w);
        }
        __syncthreads();

        unsigned long long aif[4], ago[4];
#pragma unroll
        for (int i = 0; i < 4; i++) { aif[i] = 0ull; ago[i] = 0ull; }

#pragma unroll 4
        for (int k = 0; k < 256; k++) {
            ulonglong2 wv = wsv[k * 32 + ml];        // (wi,wf),(wg,wo)
            ulonglong2 ha = hdv[k * 16 + rt * 2];    // rows r0, r0+1 (dup'd)
            ulonglong2 hb = hdv[k * 16 + rt * 2 + 1];// rows r0+2, r0+3
            aif[0] = fma2(ha.x, wv.x, aif[0]);  ago[0] = fma2(ha.x, wv.y, ago[0]);
            aif[1] = fma2(ha.y, wv.x, aif[1]);  ago[1] = fma2(ha.y, wv.y, ago[1]);
            aif[2] = fma2(hb.x, wv.x, aif[2]);  ago[2] = fma2(hb.x, wv.y, ago[2]);
            aif[3] = fma2(hb.y, wv.x, aif[3]);  ago[3] = fma2(hb.y, wv.y, ago[3]);
        }

#pragma unroll
        for (int i = 0; i < 4; i++) {
            int b = bx * 32 + rt * 4 + i;
            float zi, zf, zg, zo;
            unpack2(aif[i], zi, zf);
            unpack2(ago[i], zg, zo);
            size_t xo = ((size_t)t * B_ + b) * FM_ + mg;
            zi += g_Xk[xo];
            zf += g_Xk[xo + 256];
            zg += g_Xk[xo + 512];
            zo += g_Xk[xo + 768];
            float ig = sigm(zi), fg = sigm(zf), og = sigm(zo);
            float gg = tanh_e(zg);
            size_t so = ((size_t)t * B_ + b) * M_ + mg;
            float sn = fg * g_S[so] + ig * gg;
            float hn = og * tanh_e(sn);
            size_t dn = ((size_t)(t + 1) * B_ + b) * M_ + mg;
            g_S[dn] = sn;
            g_H[dn] = hn;
        }

        // grid barrier (protects cross-block H[t+1] dependency + smem reuse)
        __syncthreads();
        if (tid == 0) {
            __threadfence();
            unsigned long long tk = atomicAdd(&g_arrive, 1ull);
            unsigned long long gen = tk >> 7;  // /GRID_LSTM
            if ((tk & (GRID_LSTM - 1)) == GRID_LSTM - 1)
                atomicMax((unsigned long long*)&g_release, gen + 1);
            while (g_release < gen + 1) {}
            __threadfence();
        }
        __syncthreads();
    }
}

// ---- R1[tau][b][u] = concat(H,S)[tau][b] @ We[:,u] ----
__global__ __launch_bounds__(256) void k_R1(const float* __restrict__ We) {
    int rb = blockIdx.x;
    int tid = threadIdx.x;
    int u0 = (tid & 63) * 4;
    int rt = tid >> 6;
    __shared__ float as[32][64];
    float acc[8][4];
#pragma unroll
    for (int i = 0; i < 8; i++)
#pragma unroll
        for (int j = 0; j < 4; j++) acc[i][j] = 0.f;

    for (int ch = 0; ch < 8; ch++) {
        const float* src = (ch < 4) ? g_H : g_S;
        int boff = (ch & 3) * 16;
        __syncthreads();
#pragma unroll
        for (int l = 0; l < 2; l++) {
            int idx = l * 256 + tid;
            int r = idx >> 4, j4 = idx & 15;
            *(float4*)&as[r][j4 * 4] =
                ((const float4*)src)[(size_t)(rb * 32 + r) * 64 + boff + j4];
        }
        __syncthreads();
#pragma unroll 4
        for (int kk = 0; kk < 64; kk++) {
            float4 w = ((const float4*)We)[(size_t)(ch * 64 + kk) * 64 + (u0 >> 2)];
#pragma unroll
            for (int i = 0; i < 8; i++) {
                float a = as[rt * 8 + i][kk];
                acc[i][0] += a * w.x;
                acc[i][1] += a * w.y;
                acc[i][2] += a * w.z;
                acc[i][3] += a * w.w;
            }
        }
    }
#pragma unroll
    for (int i = 0; i < 8; i++) {
        ((float4*)g_R1)[(size_t)(rb * 32 + rt * 8 + i) * 64 + (u0 >> 2)] =
            make_float4(acc[i][0], acc[i][1], acc[i][2], acc[i][3]);
    }
}

// ---- fused: e = tanh(R1 + r2) @ ve ; softmax over n ; out = alpha * x ----
__global__ __launch_bounds__(512) void k_e(const float* __restrict__ x,
                                           const float* __restrict__ ve,
                                           float* __restrict__ out) {
    extern __shared__ float r2s[];   // 128 * 260 floats
    __shared__ float r1s[4][256];
    __shared__ float ves[256];
    __shared__ float redm[16];
    __shared__ float reds[16];
    int b = blockIdx.x;
    int tau0 = blockIdx.y * 32;
    int tid = threadIdx.x;
    int lane = tid & 31;
    int warp = tid >> 5;
    int q = tid >> 7;
    int n = tid & 127;

    if (tid < 256) ves[tid] = ve[tid];
#pragma unroll
    for (int l = 0; l < 16; l++) {
        int idx = l * 512 + tid;
        int nn = idx >> 6, u4 = idx & 63;
        float4 v = ((const float4*)g_r2)[(size_t)(b * N_ + nn) * 64 + u4];
        *(float4*)&r2s[nn * 260 + u4 * 4] = v;
    }
    __syncthreads();
    const float* rp = &r2s[n * 260];

    for (int ti = 0; ti < 8; ti++) {
#pragma unroll
        for (int l = 0; l < 2; l++) {
            int idx = l * 512 + tid;
            int wh = idx >> 8, u = idx & 255;
            r1s[wh][u] = g_R1[((size_t)(tau0 + ti * 4 + wh) * B_ + b) * T_ + u];
        }
        __syncthreads();
        const float* r1p = r1s[q];
        float acc0 = 0.f, acc1 = 0.f;
#pragma unroll 4
        for (int u4 = 0; u4 < 64; u4++) {
            float4 rv = *(const float4*)&rp[u4 * 4];
            float4 r1 = *(const float4*)&r1p[u4 * 4];
            float4 vv = *(const float4*)&ves[u4 * 4];
            acc0 += tanh_e(r1.x + rv.x) * vv.x;
            acc1 += tanh_e(r1.y + rv.y) * vv.y;
            acc0 += tanh_e(r1.z + rv.z) * vv.z;
            acc1 += tanh_e(r1.w + rv.w) * vv.w;
        }
        float e = acc0 + acc1;

        float mx = e;
#pragma unroll
        for (int off = 16; off >= 1; off >>= 1)
            mx = fmaxf(mx, __shfl_xor_sync(0xffffffffu, mx, off));
        if (lane == 0) redm[warp] = mx;
        __syncthreads();
        mx = fmaxf(fmaxf(redm[q * 4], redm[q * 4 + 1]),
                   fmaxf(redm[q * 4 + 2], redm[q * 4 + 3]));
        float ex = __expf(e - mx);
        float sm = ex;
#pragma unroll
        for (int off = 16; off >= 1; off >>= 1)
            sm += __shfl_xor_sync(0xffffffffu, sm, off);
        if (lane == 0) reds[warp] = sm;
        __syncthreads();
        sm = reds[q * 4] + reds[q * 4 + 1] + reds[q * 4 + 2] + reds[q * 4 + 3];
        float alpha = ex / sm;

        int tau = tau0 + ti * 4 + q;
        size_t oi = ((size_t)b * T_ + tau) * N_ + n;
        out[oi] = alpha * x[oi];
        __syncthreads();
    }
}

extern "C" void kernel_launch(void* const* d_in, const int* in_sizes, int n_in,
                              void* d_out, int out_size) {
    const float* x  = (const float*)d_in[0];
    const float* s  = (const float*)d_in[1];
    const float* h  = (const float*)d_in[2];
    const float* We = (const float*)d_in[3];
    const float* Ue = (const float*)d_in[4];
    const float* ve = (const float*)d_in[5];
    const float* Wk = (const float*)d_in[6];
    const float* Wr = (const float*)d_in[7];
    const float* bb = (const float*)d_in[8];
    float* out = (float*)d_out;
    (void)in_sizes; (void)n_in; (void)out_size;

    k_init<<<1024, 256>>>(s, h, Wr);
    k_r2<<<dim3(B_, 4), 256>>>(x, Ue);
    k_xk<<<dim3(4096, 4), 256>>>(x, Wk, bb);

    const int SML = 196608;  // 128KB weights + 64KB dup'd H
    cudaFuncSetAttribute(k_lstm_all, cudaFuncAttributeMaxDynamicSharedMemorySize, SML);
    k_lstm_all<<<GRID_LSTM, 256, SML>>>();

    k_R1<<<4096, 256>>>(We);

    const int SME = 128 * 260 * (int)sizeof(float);
    cudaFuncSetAttribute(k_e, cudaFuncAttributeMaxDynamicSharedMemorySize, SME);
    k_e<<<dim3(B_, 8), 512, SME>>>(x, ve, out);
}

// round 8
// speedup vs baseline: 2.0544x; 1.3964x over previous
#include <cuda_runtime.h>
#include <math.h>

#define B_ 512
#define T_ 256
#define N_ 128
#define M_ 256
#define FM_ 1024   // 4*M
#define GRID_LSTM 128

// ---------------- scratch (device globals: allocation-free) ----------------
__device__ float g_r2[(size_t)B_ * N_ * T_];          // [b][n][u]      67 MB
__device__ float g_Xk[(size_t)T_ * B_ * FM_];         // [t][b][4M]    537 MB
__device__ float g_H[(size_t)(T_ + 1) * B_ * M_];     // carry history 135 MB
__device__ float g_S[(size_t)(T_ + 1) * B_ * M_];     // carry history 135 MB
__device__ float g_R1[(size_t)T_ * B_ * T_];          // [tau][b][u]   134 MB
__device__ float g_Wrt[(size_t)M_ * FM_];             // Wr as [k][m][gate] 1 MB

// per-bx-group barrier state (monotone across graph replays -> deterministic)
__device__ unsigned long long g_arr[16];
__device__ unsigned long long g_rel[16];

__device__ __forceinline__ float sigm(float x) {
    return 1.0f / (1.0f + __expf(-x));
}
// accurate tanh (chain): rel err ~1e-6
__device__ __forceinline__ float tanh_e(float x) {
    float a = fabsf(x);
    float e = __expf(-2.0f * a);
    float r = __fdividef(1.0f - e, 1.0f + e);
    return copysignf(r, x);
}
// HW tanh (attention logits only)
__device__ __forceinline__ float tanh_fast(float x) {
    float y;
    asm("tanh.approx.f32 %0, %1;" : "=f"(y) : "f"(x));
    return y;
}

// ---- packed f32x2 helpers (FFMA2: B300, PTX-only path) ----
__device__ __forceinline__ unsigned long long fma2(unsigned long long a,
                                                   unsigned long long b,
                                                   unsigned long long c) {
    unsigned long long d;
    asm("fma.rn.f32x2 %0, %1, %2, %3;" : "=l"(d) : "l"(a), "l"(b), "l"(c));
    return d;
}
__device__ __forceinline__ unsigned long long dup2(float x) {
    unsigned long long r;
    asm("mov.b64 %0, {%1, %1};" : "=l"(r) : "f"(x));
    return r;
}
__device__ __forceinline__ void unpack2(unsigned long long p, float& lo, float& hi) {
    asm("mov.b64 {%0, %1}, %2;" : "=f"(lo), "=f"(hi) : "l"(p));
}

// ---- init: history slot 0 <- (h, s); transpose Wr to gate-interleaved ----
__global__ void k_init(const float* __restrict__ s, const float* __restrict__ h,
                       const float* __restrict__ Wr) {
    int i = blockIdx.x * blockDim.x + threadIdx.x;
    if (i < B_ * M_) {
        g_H[i] = h[i];
        g_S[i] = s[i];
    }
    if (i < M_ * FM_) {
        int k = i >> 10;        // Wr row 0..255
        int c = i & 1023;       // Wr col 0..1023
        int g = c >> 8;         // gate 0..3 (i,f,c,o)
        int m = c & 255;
        g_Wrt[((size_t)(k * 256 + m)) * 4 + g] = Wr[i];
    }
}

// ---- r2[b][n][u] = sum_t x[b][t][n] * Ue[t][u] ----
__global__ __launch_bounds__(256) void k_r2(const float* __restrict__ x,
                                            const float* __restrict__ Ue) {
    int b = blockIdx.x;
    int ut = blockIdx.y * 64;
    __shared__ float xs[32][128];
    __shared__ float us[32][64];
    int tid = threadIdx.x;
    int n0 = (tid & 31) * 4;
    int u0 = (tid >> 5) * 8;

    float acc[8][4];
#pragma unroll
    for (int j = 0; j < 8; j++)
#pragma unroll
        for (int i = 0; i < 4; i++) acc[j][i] = 0.f;

    for (int kt = 0; kt < T_; kt += 32) {
#pragma unroll
        for (int l = 0; l < 4; l++) {
            int idx = l * 256 + tid;
            int t = idx >> 5, n4 = idx & 31;
            *(float4*)&xs[t][n4 * 4] =
                ((const float4*)x)[(size_t)(b * T_ + kt + t) * 32 + n4];
        }
#pragma unroll
        for (int l = 0; l < 2; l++) {
            int idx = l * 256 + tid;
            int t = idx >> 4, u4 = idx & 15;
            *(float4*)&us[t][u4 * 4] =
                ((const float4*)Ue)[(size_t)(kt + t) * 64 + (ut >> 2) + u4];
        }
        __syncthreads();
#pragma unroll 8
        for (int k = 0; k < 32; k++) {
            float4 x4 = *(const float4*)&xs[k][n0];
            float4 ua = *(const float4*)&us[k][u0];
            float4 ub = *(const float4*)&us[k][u0 + 4];
            float xv[4] = {x4.x, x4.y, x4.z, x4.w};
            float uu[8] = {ua.x, ua.y, ua.z, ua.w, ub.x, ub.y, ub.z, ub.w};
#pragma unroll
            for (int j = 0; j < 8; j++)
#pragma unroll
                for (int i = 0; i < 4; i++) acc[j][i] += xv[i] * uu[j];
        }
        __syncthreads();
    }
#pragma unroll
    for (int i = 0; i < 4; i++) {
        size_t base = ((size_t)(b * N_ + n0 + i)) * T_ + ut + u0;
        *(float4*)&g_r2[base] = make_float4(acc[0][i], acc[1][i], acc[2][i], acc[3][i]);
        *(float4*)&g_r2[base + 4] = make_float4(acc[4][i], acc[5][i], acc[6][i], acc[7][i]);
    }
}

// ---- Xk[t][b][c] = x[b][t][:] @ Wk[:,c] + bias[c]  (FFMA2) ----
__global__ __launch_bounds__(256) void k_xk(const float* __restrict__ x,
                                            const float* __restrict__ Wk,
                                            const float* __restrict__ bias) {
    int rb = blockIdx.x;
    int tid = threadIdx.x;
    int c0 = blockIdx.y * 256 + (tid & 63) * 4;
    int rt = tid >> 6;
    __shared__ float as[32][128];
#pragma unroll
    for (int l = 0; l < 4; l++) {
        int idx = l * 256 + tid;
        int r = idx >> 5, n4 = idx & 31;
        *(float4*)&as[r][n4 * 4] =
            ((const float4*)x)[(size_t)(rb * 32 + r) * 32 + n4];
    }
    __syncthreads();
    unsigned long long acc[8][2];
#pragma unroll
    for (int i = 0; i < 8; i++) { acc[i][0] = 0ull; acc[i][1] = 0ull; }
#pragma unroll 4
    for (int k = 0; k < 128; k++) {
        ulonglong2 wv = *(const ulonglong2*)&Wk[(size_t)k * 1024 + c0];
#pragma unroll
        for (int i = 0; i < 8; i++) {
            unsigned long long a2 = dup2(as[rt * 8 + i][k]);
            acc[i][0] = fma2(a2, wv.x, acc[i][0]);
            acc[i][1] = fma2(a2, wv.y, acc[i][1]);
        }
    }
    float4 bv = ((const float4*)bias)[c0 >> 2];
#pragma unroll
    for (int i = 0; i < 8; i++) {
        int rbt = rb * 32 + rt * 8 + i;
        int b = rbt >> 8;
        int t = rbt & 255;
        float v0, v1, v2, v3;
        unpack2(acc[i][0], v0, v1);
        unpack2(acc[i][1], v2, v3);
        float4 v = make_float4(v0 + bv.x, v1 + bv.y, v2 + bv.z, v3 + bv.w);
        ((float4*)g_Xk)[((size_t)t * B_ + b) * 256 + (c0 >> 2)] = v;
    }
}

// ---- persistent LSTM: all 256 steps, per-bx-group barrier (8 blocks) ----
// grid 128 = 16 bx (32 b-rows) x 8 by (32 m-cols). block 256.
// smem: ws (Wr slice gate-interleaved) 128KB + hs (H[t] transposed [k][r]) 32KB.
__global__ __launch_bounds__(256, 1) void k_lstm_all() {
    extern __shared__ char smc[];
    float* ws = (float*)smc;                    // [k][32m][4g]
    float* hs = (float*)(smc + 131072);         // [k=256][r=32]
    const ulonglong2* wsv = (const ulonglong2*)ws;
    const float4* hsv = (const float4*)hs;

    int tid = threadIdx.x;
    int bx = blockIdx.x >> 3;   // 0..15 -> rows bx*32..+31  (barrier group)
    int by = blockIdx.x & 7;    // 0..7  -> m cols by*32..+31
    int ml = tid & 31;
    int mg = by * 32 + ml;
    int rt = tid >> 5;          // 0..7 -> rows rt*4..rt*4+3

    // weights into smem (once)
#pragma unroll
    for (int l = 0; l < 32; l++) {
        int f = l * 256 + tid;
        int k = f >> 5, mm = f & 31;
        ((float4*)ws)[f] = ((const float4*)g_Wrt)[(size_t)k * 256 + by * 32 + mm];
    }
    __syncthreads();

    for (int t = 0; t < T_; t++) {
        // stage H[t] transposed into hs[k][r]  (bank = r = lane: conflict-free)
#pragma unroll
        for (int l = 0; l < 8; l++) {
            int idx = l * 256 + tid;
            int r = idx & 31, j = idx >> 5;   // j = float4 col 0..63
            float4 v = ((const float4*)g_H)[((size_t)t * B_ + bx * 32 + r) * 64 + j];
            hs[(j * 4 + 0) * 32 + r] = v.x;
            hs[(j * 4 + 1) * 32 + r] = v.y;
            hs[(j * 4 + 2) * 32 + r] = v.z;
            hs[(j * 4 + 3) * 32 + r] = v.w;
        }
        // prefetch Xk + S for this step (hides DRAM latency under the GEMM)
        float px[4][4], ps[4];
#pragma unroll
        for (int i = 0; i < 4; i++) {
            int b = bx * 32 + rt * 4 + i;
            size_t xo = ((size_t)t * B_ + b) * FM_ + mg;
            px[i][0] = g_Xk[xo];
            px[i][1] = g_Xk[xo + 256];
            px[i][2] = g_Xk[xo + 512];
            px[i][3] = g_Xk[xo + 768];
            ps[i] = g_S[((size_t)t * B_ + b) * M_ + mg];
        }
        __syncthreads();

        unsigned long long aif[4], ago[4];
#pragma unroll
        for (int i = 0; i < 4; i++) { aif[i] = 0ull; ago[i] = 0ull; }

#pragma unroll 8
        for (int k = 0; k < 256; k++) {
            ulonglong2 wv = wsv[k * 32 + ml];   // (wi,wf),(wg,wo)
            float4 h4 = hsv[k * 8 + rt];        // rows rt*4..rt*4+3 (broadcast)
            unsigned long long d0 = dup2(h4.x);
            unsigned long long d1 = dup2(h4.y);
            unsigned long long d2 = dup2(h4.z);
            unsigned long long d3 = dup2(h4.w);
            aif[0] = fma2(d0, wv.x, aif[0]);  ago[0] = fma2(d0, wv.y, ago[0]);
            aif[1] = fma2(d1, wv.x, aif[1]);  ago[1] = fma2(d1, wv.y, ago[1]);
            aif[2] = fma2(d2, wv.x, aif[2]);  ago[2] = fma2(d2, wv.y, ago[2]);
            aif[3] = fma2(d3, wv.x, aif[3]);  ago[3] = fma2(d3, wv.y, ago[3]);
        }

#pragma unroll
        for (int i = 0; i < 4; i++) {
            int b = bx * 32 + rt * 4 + i;
            float zi, zf, zg, zo;
            unpack2(aif[i], zi, zf);
            unpack2(ago[i], zg, zo);
            zi += px[i][0];
            zf += px[i][1];
            zg += px[i][2];
            zo += px[i][3];
            float ig = sigm(zi), fg = sigm(zf), og = sigm(zo);
            float gg = tanh_e(zg);
            float sn = fg * ps[i] + ig * gg;
            float hn = og * tanh_e(sn);
            size_t dn = ((size_t)(t + 1) * B_ + b) * M_ + mg;
            g_S[dn] = sn;
            g_H[dn] = hn;
        }

        // per-bx barrier: only the 8 blocks sharing bx produce/consume these rows
        __syncthreads();
        if (tid == 0) {
            __threadfence();
            unsigned long long tk = atomicAdd(&g_arr[bx], 1ull);
            unsigned long long gen = tk >> 3;
            if ((tk & 7ull) == 7ull)
                atomicMax(&g_rel[bx], gen + 1);
            while (((volatile unsigned long long*)g_rel)[bx] < gen + 1) {}
            __threadfence();
        }
        __syncthreads();
    }
}

// ---- R1[tau][b][u] = concat(H,S)[tau][b] @ We[:,u]  (FFMA2) ----
__global__ __launch_bounds__(256) void k_R1(const float* __restrict__ We) {
    int rb = blockIdx.x;
    int tid = threadIdx.x;
    int u0 = (tid & 63) * 4;
    int rt = tid >> 6;
    __shared__ float as[32][64];
    unsigned long long acc[8][2];
#pragma unroll
    for (int i = 0; i < 8; i++) { acc[i][0] = 0ull; acc[i][1] = 0ull; }

    for (int ch = 0; ch < 8; ch++) {
        const float* src = (ch < 4) ? g_H : g_S;
        int boff = (ch & 3) * 16;
        __syncthreads();
#pragma unroll
        for (int l = 0; l < 2; l++) {
            int idx = l * 256 + tid;
            int r = idx >> 4, j4 = idx & 15;
            *(float4*)&as[r][j4 * 4] =
                ((const float4*)src)[(size_t)(rb * 32 + r) * 64 + boff + j4];
        }
        __syncthreads();
#pragma unroll 4
        for (int kk = 0; kk < 64; kk++) {
            ulonglong2 wv = *(const ulonglong2*)&We[(size_t)(ch * 64 + kk) * 256 + u0];
#pragma unroll
            for (int i = 0; i < 8; i++) {
                unsigned long long a2 = dup2(as[rt * 8 + i][kk]);
                acc[i][0] = fma2(a2, wv.x, acc[i][0]);
                acc[i][1] = fma2(a2, wv.y, acc[i][1]);
            }
        }
    }
#pragma unroll
    for (int i = 0; i < 8; i++) {
        float v0, v1, v2, v3;
        unpack2(acc[i][0], v0, v1);
        unpack2(acc[i][1], v2, v3);
        ((float4*)g_R1)[(size_t)(rb * 32 + rt * 8 + i) * 64 + (u0 >> 2)] =
            make_float4(v0, v1, v2, v3);
    }
}

// ---- fused: e = tanh(R1 + r2) @ ve ; softmax over n ; out = alpha * x ----
__global__ __launch_bounds__(512) void k_e(const float* __restrict__ x,
                                           const float* __restrict__ ve,
                                           float* __restrict__ out) {
    extern __shared__ float r2s[];   // 128 * 260 floats
    __shared__ float r1s[4][256];
    __shared__ float ves[256];
    __shared__ float redm[16];
    __shared__ float reds[16];
    int b = blockIdx.x;
    int tau0 = blockIdx.y * 32;
    int tid = threadIdx.x;
    int lane = tid & 31;
    int warp = tid >> 5;
    int q = tid >> 7;
    int n = tid & 127;

    if (tid < 256) ves[tid] = ve[tid];
#pragma unroll
    for (int l = 0; l < 16; l++) {
        int idx = l * 512 + tid;
        int nn = idx >> 6, u4 = idx & 63;
        float4 v = ((const float4*)g_r2)[(size_t)(b * N_ + nn) * 64 + u4];
        *(float4*)&r2s[nn * 260 + u4 * 4] = v;
    }
    __syncthreads();
    const float* rp = &r2s[n * 260];

    for (int ti = 0; ti < 8; ti++) {
#pragma unroll
        for (int l = 0; l < 2; l++) {
            int idx = l * 512 + tid;
            int wh = idx >> 8, u = idx & 255;
            r1s[wh][u] = g_R1[((size_t)(tau0 + ti * 4 + wh) * B_ + b) * T_ + u];
        }
        __syncthreads();
        const float* r1p = r1s[q];
        float acc0 = 0.f, acc1 = 0.f;
#pragma unroll 4
        for (int u4 = 0; u4 < 64; u4++) {
            float4 rv = *(const float4*)&rp[u4 * 4];
            float4 r1 = *(const float4*)&r1p[u4 * 4];
            float4 vv = *(const float4*)&ves[u4 * 4];
            acc0 += tanh_fast(r1.x + rv.x) * vv.x;
            acc1 += tanh_fast(r1.y + rv.y) * vv.y;
            acc0 += tanh_fast(r1.z + rv.z) * vv.z;
            acc1 += tanh_fast(r1.w + rv.w) * vv.w;
        }
        float e = acc0 + acc1;

        float mx = e;
#pragma unroll
        for (int off = 16; off >= 1; off >>= 1)
            mx = fmaxf(mx, __shfl_xor_sync(0xffffffffu, mx, off));
        if (lane == 0) redm[warp] = mx;
        __syncthreads();
        mx = fmaxf(fmaxf(redm[q * 4], redm[q * 4 + 1]),
                   fmaxf(redm[q * 4 + 2], redm[q * 4 + 3]));
        float ex = __expf(e - mx);
        float sm = ex;
#pragma unroll
        for (int off = 16; off >= 1; off >>= 1)
            sm += __shfl_xor_sync(0xffffffffu, sm, off);
        if (lane == 0) reds[warp] = sm;
        __syncthreads();
        sm = reds[q * 4] + reds[q * 4 + 1] + reds[q * 4 + 2] + reds[q * 4 + 3];
        float alpha = ex / sm;

        int tau = tau0 + ti * 4 + q;
        size_t oi = ((size_t)b * T_ + tau) * N_ + n;
        out[oi] = alpha * x[oi];
        __syncthreads();
    }
}

extern "C" void kernel_launch(void* const* d_in, const int* in_sizes, int n_in,
                              void* d_out, int out_size) {
    const float* x  = (const float*)d_in[0];
    const float* s  = (const float*)d_in[1];
    const float* h  = (const float*)d_in[2];
    const float* We = (const float*)d_in[3];
    const float* Ue = (const float*)d_in[4];
    const float* ve = (const float*)d_in[5];
    const float* Wk = (const float*)d_in[6];
    const float* Wr = (const float*)d_in[7];
    const float* bb = (const float*)d_in[8];
    float* out = (float*)d_out;
    (void)in_sizes; (void)n_in; (void)out_size;

    k_init<<<1024, 256>>>(s, h, Wr);
    k_r2<<<dim3(B_, 4), 256>>>(x, Ue);
    k_xk<<<dim3(4096, 4), 256>>>(x, Wk, bb);

    const int SML = 131072 + 32768;  // 128KB weights + 32KB transposed H
    cudaFuncSetAttribute(k_lstm_all, cudaFuncAttributeMaxDynamicSharedMemorySize, SML);
    k_lstm_all<<<GRID_LSTM, 256, SML>>>();

    k_R1<<<4096, 256>>>(We);

    const int SME = 128 * 260 * (int)sizeof(float);
    cudaFuncSetAttribute(k_e, cudaFuncAttributeMaxDynamicSharedMemorySize, SME);
    k_e<<<dim3(B_, 8), 512, SME>>>(x, ve, out);
}

// round 9
// speedup vs baseline: 2.0706x; 1.0079x over previous
#include <cuda_runtime.h>
#include <math.h>

#define B_ 512
#define T_ 256
#define N_ 128
#define M_ 256
#define FM_ 1024   // 4*M
#define GRID_LSTM 128

// ---------------- scratch (device globals: allocation-free) ----------------
__device__ float g_r2[(size_t)B_ * N_ * T_];            // [b][n][u]       67 MB
__device__ float g_Xk[(size_t)T_ * B_ * FM_];           // [t][b][4M]     537 MB
__device__ float g_H[(size_t)(T_ + 1) * B_ * M_];       // row-layout hist 135 MB
__device__ float g_S[(size_t)(T_ + 1) * B_ * M_];       // row-layout hist 135 MB
__device__ float g_Ht[(size_t)(T_ + 1) * 16 * M_ * 32]; // [t][bx][k][r]  135 MB
__device__ float g_R1[(size_t)T_ * B_ * T_];            // [tau][b][u]    134 MB
__device__ float g_Wrt[(size_t)M_ * FM_];               // Wr [k][m][gate]  1 MB

// per-bx-group arrival counters (zeroed by k_init each launch -> replay-safe)
__device__ unsigned long long g_arr[16];

__device__ __forceinline__ float sigm(float x) {
    return 1.0f / (1.0f + __expf(-x));
}
// accurate tanh (chain): rel err ~1e-6
__device__ __forceinline__ float tanh_e(float x) {
    float a = fabsf(x);
    float e = __expf(-2.0f * a);
    float r = __fdividef(1.0f - e, 1.0f + e);
    return copysignf(r, x);
}
// HW tanh (attention logits only)
__device__ __forceinline__ float tanh_fast(float x) {
    float y;
    asm("tanh.approx.f32 %0, %1;" : "=f"(y) : "f"(x));
    return y;
}

// ---- packed f32x2 helpers (FFMA2: B300, PTX-only path) ----
__device__ __forceinline__ unsigned long long fma2(unsigned long long a,
                                                   unsigned long long b,
                                                   unsigned long long c) {
    unsigned long long d;
    asm("fma.rn.f32x2 %0, %1, %2, %3;" : "=l"(d) : "l"(a), "l"(b), "l"(c));
    return d;
}
__device__ __forceinline__ unsigned long long add2(unsigned long long a,
                                                   unsigned long long b) {
    unsigned long long d;
    asm("add.rn.f32x2 %0, %1, %2;" : "=l"(d) : "l"(a), "l"(b));
    return d;
}
__device__ __forceinline__ unsigned long long dup2(float x) {
    unsigned long long r;
    asm("mov.b64 %0, {%1, %1};" : "=l"(r) : "f"(x));
    return r;
}
__device__ __forceinline__ void unpack2(unsigned long long p, float& lo, float& hi) {
    asm("mov.b64 {%0, %1}, %2;" : "=f"(lo), "=f"(hi) : "l"(p));
}

// ---- init: slot 0 <- (h, s) in both layouts; Wr gate-interleave; reset bars ----
__global__ void k_init(const float* __restrict__ s, const float* __restrict__ h,
                       const float* __restrict__ Wr) {
    int i = blockIdx.x * blockDim.x + threadIdx.x;
    if (i < B_ * M_) {
        g_H[i] = h[i];
        g_S[i] = s[i];
        int b = i >> 8;       // row
        int m = i & 255;      // col
        int bx = b >> 5, r = b & 31;
        g_Ht[((size_t)bx * 256 + m) * 32 + r] = h[i];
    }
    if (i < M_ * FM_) {
        int k = i >> 10;
        int c = i & 1023;
        int g = c >> 8;       // gate 0..3 (i,f,c,o)
        int m = c & 255;
        g_Wrt[((size_t)(k * 256 + m)) * 4 + g] = Wr[i];
    }
    if (i < 16) g_arr[i] = 0ull;
}

// ---- r2[b][n][u] = sum_t x[b][t][n] * Ue[t][u] ----
__global__ __launch_bounds__(256) void k_r2(const float* __restrict__ x,
                                            const float* __restrict__ Ue) {
    int b = blockIdx.x;
    int ut = blockIdx.y * 64;
    __shared__ float xs[32][128];
    __shared__ float us[32][64];
    int tid = threadIdx.x;
    int n0 = (tid & 31) * 4;
    int u0 = (tid >> 5) * 8;

    float acc[8][4];
#pragma unroll
    for (int j = 0; j < 8; j++)
#pragma unroll
        for (int i = 0; i < 4; i++) acc[j][i] = 0.f;

    for (int kt = 0; kt < T_; kt += 32) {
#pragma unroll
        for (int l = 0; l < 4; l++) {
            int idx = l * 256 + tid;
            int t = idx >> 5, n4 = idx & 31;
            *(float4*)&xs[t][n4 * 4] =
                ((const float4*)x)[(size_t)(b * T_ + kt + t) * 32 + n4];
        }
#pragma unroll
        for (int l = 0; l < 2; l++) {
            int idx = l * 256 + tid;
            int t = idx >> 4, u4 = idx & 15;
            *(float4*)&us[t][u4 * 4] =
                ((const float4*)Ue)[(size_t)(kt + t) * 64 + (ut >> 2) + u4];
        }
        __syncthreads();
#pragma unroll 8
        for (int k = 0; k < 32; k++) {
            float4 x4 = *(const float4*)&xs[k][n0];
            float4 ua = *(const float4*)&us[k][u0];
            float4 ub = *(const float4*)&us[k][u0 + 4];
            float xv[4] = {x4.x, x4.y, x4.z, x4.w};
            float uu[8] = {ua.x, ua.y, ua.z, ua.w, ub.x, ub.y, ub.z, ub.w};
#pragma unroll
            for (int j = 0; j < 8; j++)
#pragma unroll
                for (int i = 0; i < 4; i++) acc[j][i] += xv[i] * uu[j];
        }
        __syncthreads();
    }
#pragma unroll
    for (int i = 0; i < 4; i++) {
        size_t base = ((size_t)(b * N_ + n0 + i)) * T_ + ut + u0;
        *(float4*)&g_r2[base] = make_float4(acc[0][i], acc[1][i], acc[2][i], acc[3][i]);
        *(float4*)&g_r2[base + 4] = make_float4(acc[4][i], acc[5][i], acc[6][i], acc[7][i]);
    }
}

// ---- Xk[t][b][c] = x[b][t][:] @ Wk[:,c] + bias[c]  (FFMA2) ----
__global__ __launch_bounds__(256) void k_xk(const float* __restrict__ x,
                                            const float* __restrict__ Wk,
                                            const float* __restrict__ bias) {
    int rb = blockIdx.x;
    int tid = threadIdx.x;
    int c0 = blockIdx.y * 256 + (tid & 63) * 4;
    int rt = tid >> 6;
    __shared__ float as[32][128];
#pragma unroll
    for (int l = 0; l < 4; l++) {
        int idx = l * 256 + tid;
        int r = idx >> 5, n4 = idx & 31;
        *(float4*)&as[r][n4 * 4] =
            ((const float4*)x)[(size_t)(rb * 32 + r) * 32 + n4];
    }
    __syncthreads();
    unsigned long long acc[8][2];
#pragma unroll
    for (int i = 0; i < 8; i++) { acc[i][0] = 0ull; acc[i][1] = 0ull; }
#pragma unroll 4
    for (int k = 0; k < 128; k++) {
        ulonglong2 wv = *(const ulonglong2*)&Wk[(size_t)k * 1024 + c0];
#pragma unroll
        for (int i = 0; i < 8; i++) {
            unsigned long long a2 = dup2(as[rt * 8 + i][k]);
            acc[i][0] = fma2(a2, wv.x, acc[i][0]);
            acc[i][1] = fma2(a2, wv.y, acc[i][1]);
        }
    }
    float4 bv = ((const float4*)bias)[c0 >> 2];
#pragma unroll
    for (int i = 0; i < 8; i++) {
        int rbt = rb * 32 + rt * 8 + i;
        int b = rbt >> 8;
        int t = rbt & 255;
        float v0, v1, v2, v3;
        unpack2(acc[i][0], v0, v1);
        unpack2(acc[i][1], v2, v3);
        float4 v = make_float4(v0 + bv.x, v1 + bv.y, v2 + bv.z, v3 + bv.w);
        ((float4*)g_Xk)[((size_t)t * B_ + b) * 256 + (c0 >> 2)] = v;
    }
}

// ---- persistent LSTM: 512 threads, k-split halves, per-bx one-hop barrier ----
// grid 128 = 16 bx (32 b-rows) x 8 by (32 m-cols). block 512 = 16 warps.
// smem: ws 128KB (Wr slice) + hs 32KB (H[t] transposed; doubles as partial buf).
__global__ __launch_bounds__(512, 1) void k_lstm_all() {
    extern __shared__ char smc[];
    float* ws = (float*)smc;                                  // [k][32m][4g]
    float* hs = (float*)(smc + 131072);                       // [k=256][r=32]
    unsigned long long* pp = (unsigned long long*)(smc + 131072);
    const ulonglong2* wsv = (const ulonglong2*)ws;
    const float4* hsv = (const float4*)hs;

    int tid = threadIdx.x;
    int bx = blockIdx.x >> 3;   // barrier group (rows bx*32..+31)
    int by = blockIdx.x & 7;    // m cols by*32..+31
    int ml = tid & 31;
    int mg = by * 32 + ml;
    int rt = (tid >> 5) & 7;    // rows rt*4..+3
    int kh = tid >> 8;          // k-half 0/1
    int k0 = kh * 128;

    // weights into smem (once)
#pragma unroll
    for (int l = 0; l < 16; l++) {
        int f = l * 512 + tid;
        int k = f >> 5, mm = f & 31;
        ((float4*)ws)[f] = ((const float4*)g_Wrt)[(size_t)k * 256 + by * 32 + mm];
    }

    // s carry in registers + first Xk prefetch (kh0 threads own the epilogue)
    float s4[4];
    float px[4][4];
    if (kh == 0) {
#pragma unroll
        for (int i = 0; i < 4; i++) {
            int b = bx * 32 + rt * 4 + i;
            s4[i] = g_S[(size_t)b * M_ + mg];
            size_t xo = (size_t)b * FM_ + mg;
            px[i][0] = g_Xk[xo];
            px[i][1] = g_Xk[xo + 256];
            px[i][2] = g_Xk[xo + 512];
            px[i][3] = g_Xk[xo + 768];
        }
    }
    // stage H[0] (already transposed by k_init)
#pragma unroll
    for (int l = 0; l < 4; l++) {
        int idx = l * 512 + tid;
        ((float4*)hs)[idx] = ((const float4*)g_Ht)[(size_t)bx * 2048 + idx];
    }
    __syncthreads();

    for (int t = 0; t < T_; t++) {
        unsigned long long aif[4], ago[4];
#pragma unroll
        for (int i = 0; i < 4; i++) { aif[i] = 0ull; ago[i] = 0ull; }

#pragma unroll 8
        for (int kk = 0; kk < 128; kk++) {
            int k = k0 + kk;
            ulonglong2 wv = wsv[k * 32 + ml];   // (wi,wf),(wg,wo)
            float4 h4 = hsv[k * 8 + rt];        // rows rt*4..+3 (broadcast)
            unsigned long long d0 = dup2(h4.x);
            unsigned long long d1 = dup2(h4.y);
            unsigned long long d2 = dup2(h4.z);
            unsigned long long d3 = dup2(h4.w);
            aif[0] = fma2(d0, wv.x, aif[0]);  ago[0] = fma2(d0, wv.y, ago[0]);
            aif[1] = fma2(d1, wv.x, aif[1]);  ago[1] = fma2(d1, wv.y, ago[1]);
            aif[2] = fma2(d2, wv.x, aif[2]);  ago[2] = fma2(d2, wv.y, ago[2]);
            aif[3] = fma2(d3, wv.x, aif[3]);  ago[3] = fma2(d3, wv.y, ago[3]);
        }
        __syncthreads();   // hs reads complete before pp overwrite

        if (kh == 1) {
            int o = (tid - 256) * 8;
            pp[o + 0] = aif[0]; pp[o + 1] = aif[1];
            pp[o + 2] = aif[2]; pp[o + 3] = aif[3];
            pp[o + 4] = ago[0]; pp[o + 5] = ago[1];
            pp[o + 6] = ago[2]; pp[o + 7] = ago[3];
        }
        __syncthreads();

        if (kh == 0) {
            int o = tid * 8;
            float hv[4];
#pragma unroll
            for (int i = 0; i < 4; i++) {
                unsigned long long zif = add2(aif[i], pp[o + i]);
                unsigned long long zgo = add2(ago[i], pp[o + 4 + i]);
                int b = bx * 32 + rt * 4 + i;
                float zi, zf, zg, zo;
                unpack2(zif, zi, zf);
                unpack2(zgo, zg, zo);
                zi += px[i][0];
                zf += px[i][1];
                zg += px[i][2];
                zo += px[i][3];
                float ig = sigm(zi), fg = sigm(zf), og = sigm(zo);
                float gg = tanh_e(zg);
                float sn = fg * s4[i] + ig * gg;
                float hn = og * tanh_e(sn);
                s4[i] = sn;
                hv[i] = hn;
                size_t dn = ((size_t)(t + 1) * B_ + b) * M_ + mg;
                g_S[dn] = sn;
                g_H[dn] = hn;
            }
            // transposed store for next-step staging: one STG.128
            ((float4*)g_Ht)[(((size_t)(t + 1) * 16 + bx) * 256 + mg) * 8 + rt] =
                make_float4(hv[0], hv[1], hv[2], hv[3]);
            // prefetch next step's Xk (lands during spin/stage)
            int tn = t < T_ - 1 ? t + 1 : t;
#pragma unroll
            for (int i = 0; i < 4; i++) {
                int b = bx * 32 + rt * 4 + i;
                size_t xo = ((size_t)tn * B_ + b) * FM_ + mg;
                px[i][0] = g_Xk[xo];
                px[i][1] = g_Xk[xo + 256];
                px[i][2] = g_Xk[xo + 512];
                px[i][3] = g_Xk[xo + 768];
            }
        }
        __syncthreads();   // all stores issued before arrive

        if (tid == 0) {
            __threadfence();
            atomicAdd(&g_arr[bx], 1ull);
        }
        unsigned long long tgt = 8ull * (unsigned long long)(t + 1);
        while (*((volatile unsigned long long*)&g_arr[bx]) < tgt) {}

        // stage H[t+1]
#pragma unroll
        for (int l = 0; l < 4; l++) {
            int idx = l * 512 + tid;
            ((float4*)hs)[idx] =
                ((const float4*)g_Ht)[((size_t)(t + 1) * 16 + bx) * 2048 + idx];
        }
        __syncthreads();
    }
}

// ---- R1[tau][b][u] = concat(H,S)[tau][b] @ We[:,u]  (FFMA2) ----
__global__ __launch_bounds__(256) void k_R1(const float* __restrict__ We) {
    int rb = blockIdx.x;
    int tid = threadIdx.x;
    int u0 = (tid & 63) * 4;
    int rt = tid >> 6;
    __shared__ float as[32][64];
    unsigned long long acc[8][2];
#pragma unroll
    for (int i = 0; i < 8; i++) { acc[i][0] = 0ull; acc[i][1] = 0ull; }

    for (int ch = 0; ch < 8; ch++) {
        const float* src = (ch < 4) ? g_H : g_S;
        int boff = (ch & 3) * 16;
        __syncthreads();
#pragma unroll
        for (int l = 0; l < 2; l++) {
            int idx = l * 256 + tid;
            int r = idx >> 4, j4 = idx & 15;
            *(float4*)&as[r][j4 * 4] =
                ((const float4*)src)[(size_t)(rb * 32 + r) * 64 + boff + j4];
        }
        __syncthreads();
#pragma unroll 4
        for (int kk = 0; kk < 64; kk++) {
            ulonglong2 wv = *(const ulonglong2*)&We[(size_t)(ch * 64 + kk) * 256 + u0];
#pragma unroll
            for (int i = 0; i < 8; i++) {
                unsigned long long a2 = dup2(as[rt * 8 + i][kk]);
                acc[i][0] = fma2(a2, wv.x, acc[i][0]);
                acc[i][1] = fma2(a2, wv.y, acc[i][1]);
            }
        }
    }
#pragma unroll
    for (int i = 0; i < 8; i++) {
        float v0, v1, v2, v3;
        unpack2(acc[i][0], v0, v1);
        unpack2(acc[i][1], v2, v3);
        ((float4*)g_R1)[(size_t)(rb * 32 + rt * 8 + i) * 64 + (u0 >> 2)] =
            make_float4(v0, v1, v2, v3);
    }
}

// ---- fused: e = tanh(R1 + r2) @ ve ; softmax over n ; out = alpha * x ----
__global__ __launch_bounds__(512) void k_e(const float* __restrict__ x,
                                           const float* __restrict__ ve,
                                           float* __restrict__ out) {
    extern __shared__ float r2s[];   // 128 * 260 floats
    __shared__ float r1s[4][256];
    __shared__ float ves[256];
    __shared__ float redm[16];
    __shared__ float reds[16];
    int b = blockIdx.x;
    int tau0 = blockIdx.y * 32;
    int tid = threadIdx.x;
    int lane = tid & 31;
    int warp = tid >> 5;
    int q = tid >> 7;
    int n = tid & 127;

    if (tid < 256) ves[tid] = ve[tid];
#pragma unroll
    for (int l = 0; l < 16; l++) {
        int idx = l * 512 + tid;
        int nn = idx >> 6, u4 = idx & 63;
        float4 v = ((const float4*)g_r2)[(size_t)(b * N_ + nn) * 64 + u4];
        *(float4*)&r2s[nn * 260 + u4 * 4] = v;
    }
    __syncthreads();
    const float* rp = &r2s[n * 260];

    for (int ti = 0; ti < 8; ti++) {
#pragma unroll
        for (int l = 0; l < 2; l++) {
            int idx = l * 512 + tid;
            int wh = idx >> 8, u = idx & 255;
            r1s[wh][u] = g_R1[((size_t)(tau0 + ti * 4 + wh) * B_ + b) * T_ + u];
        }
        __syncthreads();
        const float* r1p = r1s[q];
        float acc0 = 0.f, acc1 = 0.f;
#pragma unroll 4
        for (int u4 = 0; u4 < 64; u4++) {
            float4 rv = *(const float4*)&rp[u4 * 4];
            float4 r1 = *(const float4*)&r1p[u4 * 4];
            float4 vv = *(const float4*)&ves[u4 * 4];
            acc0 += tanh_fast(r1.x + rv.x) * vv.x;
            acc1 += tanh_fast(r1.y + rv.y) * vv.y;
            acc0 += tanh_fast(r1.z + rv.z) * vv.z;
            acc1 += tanh_fast(r1.w + rv.w) * vv.w;
        }
        float e = acc0 + acc1;

        float mx = e;
#pragma unroll
        for (int off = 16; off >= 1; off >>= 1)
            mx = fmaxf(mx, __shfl_xor_sync(0xffffffffu, mx, off));
        if (lane == 0) redm[warp] = mx;
        __syncthreads();
        mx = fmaxf(fmaxf(redm[q * 4], redm[q * 4 + 1]),
                   fmaxf(redm[q * 4 + 2], redm[q * 4 + 3]));
        float ex = __expf(e - mx);
        float sm = ex;
#pragma unroll
        for (int off = 16; off >= 1; off >>= 1)
            sm += __shfl_xor_sync(0xffffffffu, sm, off);
        if (lane == 0) reds[warp] = sm;
        __syncthreads();
        sm = reds[q * 4] + reds[q * 4 + 1] + reds[q * 4 + 2] + reds[q * 4 + 3];
        float alpha = ex / sm;

        int tau = tau0 + ti * 4 + q;
        size_t oi = ((size_t)b * T_ + tau) * N_ + n;
        out[oi] = alpha * x[oi];
        __syncthreads();
    }
}

extern "C" void kernel_launch(void* const* d_in, const int* in_sizes, int n_in,
                              void* d_out, int out_size) {
    const float* x  = (const float*)d_in[0];
    const float* s  = (const float*)d_in[1];
    const float* h  = (const float*)d_in[2];
    const float* We = (const float*)d_in[3];
    const float* Ue = (const float*)d_in[4];
    const float* ve = (const float*)d_in[5];
    const float* Wk = (const float*)d_in[6];
    const float* Wr = (const float*)d_in[7];
    const float* bb = (const float*)d_in[8];
    float* out = (float*)d_out;
    (void)in_sizes; (void)n_in; (void)out_size;

    k_init<<<1024, 256>>>(s, h, Wr);
    k_r2<<<dim3(B_, 4), 256>>>(x, Ue);
    k_xk<<<dim3(4096, 4), 256>>>(x, Wk, bb);

    const int SML = 131072 + 32768;  // 128KB weights + 32KB H/partials
    cudaFuncSetAttribute(k_lstm_all, cudaFuncAttributeMaxDynamicSharedMemorySize, SML);
    k_lstm_all<<<GRID_LSTM, 512, SML>>>();

    k_R1<<<4096, 256>>>(We);

    const int SME = 128 * 260 * (int)sizeof(float);
    cudaFuncSetAttribute(k_e, cudaFuncAttributeMaxDynamicSharedMemorySize, SME);
    k_e<<<dim3(B_, 8), 512, SME>>>(x, ve, out);
}